// round 7
// baseline (speedup 1.0000x reference)
#include <cuda_runtime.h>

// JPEG compress/decompress (DiffJPEG, factor=1.0) for [16,3,512,512] fp32 in [-1,1].
// One CTA = one 64x32 tile, 256 threads, 6 CTAs/SM (reg-capped at 42).
// Lane-pair row transforms: lanes (2j,2j+1) share one 8-pixel row segment via
// shfl_xor(1) butterflies; each lane computes 4 of 8 frequencies (even lane:
// 0,2,4,6; odd lane: 1,3,5,7), stored permuted. Quant tables pre-permuted.
// Phase 1: gmem -> YCbCr -> half row-DCT -> smem   (channel-serial, low regs)
// Phase 2: column DCT + diff-round quant + column IDCT (scalar, conflict-free)
// Phase 3: smem -> half row-IDCT -> YCbCr->RGB -> gmem
// DC trick: subtract 128*64 from the DC coefficient; re-add 128 at output.

namespace {

constexpr int Hh = 512;
constexpr int Ww = 512;
constexpr int TW = 64;    // tile width
constexpr int TH = 32;    // tile height
constexpr int PL = TW * TH;   // plane floats per channel = 2048

// Forward half-transform coefs: CF[p][m][k] = Dm[2m+p][k], k=0..3
__constant__ float CF[32] = {
  // p=0 (even lanes): rows Dm[0], Dm[2], Dm[4], Dm[6]
  1.f,          1.f,          1.f,          1.f,
  0.92387953f,  0.38268343f, -0.38268343f, -0.92387953f,
  0.70710678f, -0.70710678f, -0.70710678f,  0.70710678f,
  0.38268343f, -0.92387953f,  0.92387953f, -0.38268343f,
  // p=1 (odd lanes): rows Dm[1], Dm[3], Dm[5], Dm[7]
  0.98078528f,  0.83146961f,  0.55557023f,  0.19509032f,
  0.83146961f, -0.19509032f, -0.98078528f, -0.55557023f,
  0.55557023f, -0.98078528f,  0.19509032f,  0.83146961f,
  0.19509032f, -0.55557023f,  0.83146961f, -0.98078528f,
};
// Inverse half-transform coefs: CI[p][k][m] = Dm[2m+p][k]
__constant__ float CI[32] = {
  1.f,  0.92387953f,  0.70710678f,  0.38268343f,
  1.f,  0.38268343f, -0.70710678f, -0.92387953f,
  1.f, -0.38268343f, -0.70710678f,  0.92387953f,
  1.f, -0.92387953f,  0.70710678f, -0.38268343f,
  0.98078528f,  0.83146961f,  0.55557023f,  0.19509032f,
  0.83146961f, -0.19509032f, -0.98078528f, -0.55557023f,
  0.55557023f, -0.98078528f,  0.19509032f,  0.83146961f,
  0.19509032f, -0.55557023f,  0.83146961f, -0.98078528f,
};

// Full 8-point DCT basis for the column pass
__device__ static constexpr float Dm[8][8] = {
  { 1.f,          1.f,          1.f,          1.f,          1.f,          1.f,          1.f,          1.f         },
  { 0.98078528f,  0.83146961f,  0.55557023f,  0.19509032f, -0.19509032f, -0.55557023f, -0.83146961f, -0.98078528f },
  { 0.92387953f,  0.38268343f, -0.38268343f, -0.92387953f, -0.92387953f, -0.38268343f,  0.38268343f,  0.92387953f },
  { 0.83146961f, -0.19509032f, -0.98078528f, -0.55557023f,  0.55557023f,  0.98078528f,  0.19509032f, -0.83146961f },
  { 0.70710678f, -0.70710678f, -0.70710678f,  0.70710678f,  0.70710678f, -0.70710678f, -0.70710678f,  0.70710678f },
  { 0.55557023f, -0.98078528f,  0.19509032f,  0.83146961f, -0.83146961f, -0.19509032f,  0.98078528f, -0.55557023f },
  { 0.38268343f, -0.92387953f,  0.92387953f, -0.38268343f, -0.38268343f,  0.92387953f, -0.92387953f,  0.38268343f },
  { 0.19509032f, -0.55557023f,  0.83146961f, -0.98078528f,  0.98078528f, -0.83146961f,  0.55557023f, -0.19509032f },
};

__device__ static const float QY[64] = {
  16, 11, 10, 16, 24, 40, 51, 61,
  12, 12, 14, 19, 26, 58, 60, 55,
  14, 13, 16, 24, 40, 57, 69, 56,
  14, 17, 22, 29, 51, 87, 80, 62,
  18, 22, 37, 56, 68, 109, 103, 77,
  24, 35, 55, 64, 81, 104, 113, 92,
  49, 64, 78, 87, 103, 121, 120, 101,
  72, 92, 95, 98, 112, 100, 103, 99
};
__device__ static const float QC[64] = {
  17, 18, 24, 47, 99, 99, 99, 99,
  18, 21, 26, 66, 99, 99, 99, 99,
  24, 26, 56, 99, 99, 99, 99, 99,
  47, 66, 99, 99, 99, 99, 99, 99,
  99, 99, 99, 99, 99, 99, 99, 99,
  99, 99, 99, 99, 99, 99, 99, 99,
  99, 99, 99, 99, 99, 99, 99, 99,
  99, 99, 99, 99, 99, 99, 99, 99
};

__device__ __forceinline__ int swzc(int c) { return c ^ ((c & 32) >> 3); }

__device__ __forceinline__ void dct1(float* v) {
  float e0 = v[0] + v[7], e1 = v[1] + v[6], e2 = v[2] + v[5], e3 = v[3] + v[4];
  float o0 = v[0] - v[7], o1 = v[1] - v[6], o2 = v[2] - v[5], o3 = v[3] - v[4];
  v[0] = (e0 + e3) + (e1 + e2);
  v[4] = Dm[4][0] * ((e0 + e3) - (e1 + e2));
  v[2] = Dm[2][0]*e0 + Dm[2][1]*e1 + Dm[2][2]*e2 + Dm[2][3]*e3;
  v[6] = Dm[6][0]*e0 + Dm[6][1]*e1 + Dm[6][2]*e2 + Dm[6][3]*e3;
  v[1] = Dm[1][0]*o0 + Dm[1][1]*o1 + Dm[1][2]*o2 + Dm[1][3]*o3;
  v[3] = Dm[3][0]*o0 + Dm[3][1]*o1 + Dm[3][2]*o2 + Dm[3][3]*o3;
  v[5] = Dm[5][0]*o0 + Dm[5][1]*o1 + Dm[5][2]*o2 + Dm[5][3]*o3;
  v[7] = Dm[7][0]*o0 + Dm[7][1]*o1 + Dm[7][2]*o2 + Dm[7][3]*o3;
}
__device__ __forceinline__ void idct1(float* v) {
  float i0 = v[0], i1 = v[1], i2 = v[2], i3 = v[3];
  float i4 = v[4], i5 = v[5], i6 = v[6], i7 = v[7];
#pragma unroll
  for (int k = 0; k < 4; ++k) {
    float ev = i0 + Dm[2][k]*i2 + Dm[4][k]*i4 + Dm[6][k]*i6;
    float od = Dm[1][k]*i1 + Dm[3][k]*i3 + Dm[5][k]*i5 + Dm[7][k]*i7;
    v[k]     = ev + od;
    v[7 - k] = ev - od;
  }
}

// Lane-pair half row-DCT (even lane: natural px, odd lane: reversed px)
__device__ __forceinline__ void half_dct(float v[4], const float cf[16], float sgn) {
  float t0 = __shfl_xor_sync(0xffffffffu, v[0], 1);
  float t1 = __shfl_xor_sync(0xffffffffu, v[1], 1);
  float t2 = __shfl_xor_sync(0xffffffffu, v[2], 1);
  float t3 = __shfl_xor_sync(0xffffffffu, v[3], 1);
  float x0 = fmaf(sgn, v[0], t0);
  float x1 = fmaf(sgn, v[1], t1);
  float x2 = fmaf(sgn, v[2], t2);
  float x3 = fmaf(sgn, v[3], t3);
  v[0] = fmaf(cf[3],  x3, fmaf(cf[2],  x2, fmaf(cf[1],  x1, cf[0]  * x0)));
  v[1] = fmaf(cf[7],  x3, fmaf(cf[6],  x2, fmaf(cf[5],  x1, cf[4]  * x0)));
  v[2] = fmaf(cf[11], x3, fmaf(cf[10], x2, fmaf(cf[9],  x1, cf[8]  * x0)));
  v[3] = fmaf(cf[15], x3, fmaf(cf[14], x2, fmaf(cf[13], x1, cf[12] * x0)));
}

// Lane-pair half row-IDCT (even lane out: natural px, odd lane out: reversed px)
__device__ __forceinline__ void half_idct(float f[4], const float ci[16], float sgn) {
  float g0 = fmaf(ci[3],  f[3], fmaf(ci[2],  f[2], fmaf(ci[1],  f[1], ci[0]  * f[0])));
  float g1 = fmaf(ci[7],  f[3], fmaf(ci[6],  f[2], fmaf(ci[5],  f[1], ci[4]  * f[0])));
  float g2 = fmaf(ci[11], f[3], fmaf(ci[10], f[2], fmaf(ci[9],  f[1], ci[8]  * f[0])));
  float g3 = fmaf(ci[15], f[3], fmaf(ci[14], f[2], fmaf(ci[13], f[1], ci[12] * f[0])));
  float t0 = __shfl_xor_sync(0xffffffffu, g0, 1);
  float t1 = __shfl_xor_sync(0xffffffffu, g1, 1);
  float t2 = __shfl_xor_sync(0xffffffffu, g2, 1);
  float t3 = __shfl_xor_sync(0xffffffffu, g3, 1);
  f[0] = fmaf(sgn, g0, t0);
  f[1] = fmaf(sgn, g1, t1);
  f[2] = fmaf(sgn, g2, t2);
  f[3] = fmaf(sgn, g3, t3);
}

__global__ void __launch_bounds__(256, 6)
jpeg_kernel(const float* __restrict__ in, float* __restrict__ out) {
  extern __shared__ float sm[];         // 3*2048 planes + 128 SA + 128 SB
  float* sQA = sm + 3 * PL;             // permuted: 0.25*au*av / Q
  float* sQB = sm + 3 * PL + 128;       // permuted: 0.25*au*av * Q

  const int tid = threadIdx.x;
  const bool oddl = (tid & 1) != 0;
  const float sgn = oddl ? -1.f : 1.f;
  const int gx0 = blockIdx.x * TW;
  const int gy0 = blockIdx.y * TH;
  const size_t plane = (size_t)Hh * Ww;
  const size_t img = (size_t)blockIdx.z * 3 * plane;
  const float* __restrict__ pr = in + img;
  const float* __restrict__ pg = in + img + plane;
  const float* __restrict__ pb = in + img + 2 * plane;

  // ---- quant table fill (slot s holds freq perm[s] = {0,2,4,6,1,3,5,7}) ----
  if (tid < 128) {
    int tab = tid >> 6, uv = tid & 63, u = uv >> 3, s = uv & 7;
    int v = (s < 4) ? (s << 1) : ((s << 1) - 7);
    float a = 0.25f * (u ? 1.f : 0.70710678118654752f)
                    * (v ? 1.f : 0.70710678118654752f);
    float Q = tab ? QC[u * 8 + v] : QY[u * 8 + v];
    sQA[tid] = a / Q;
    sQB[tid] = a * Q;
  }

  // ------- Phase 1: gmem -> YCbCr -> half row-DCT -> smem (channel-serial) -------
  {
    float cf[16];
    const float* cfp = CF + (oddl ? 16 : 0);
#pragma unroll
    for (int t = 0; t < 16; ++t) cf[t] = cfp[t];

#pragma unroll
    for (int it = 0; it < 2; ++it) {
      int i = tid + it * 256;
      int row = i >> 4;                 // 0..31
      int c4 = (i & 15) << 2;
      size_t g = (size_t)(gy0 + row) * Ww + (gx0 + c4);
      float4 r4 = *(const float4*)(pr + g);
      float4 g4 = *(const float4*)(pg + g);
      float4 b4 = *(const float4*)(pb + g);

      // odd lanes reverse their 4 pixels (pixel order 8j+7..8j+4)
      float R[4], G[4], B[4];
      R[0] = oddl ? r4.w : r4.x;  R[1] = oddl ? r4.z : r4.y;
      R[2] = oddl ? r4.y : r4.z;  R[3] = oddl ? r4.x : r4.w;
      G[0] = oddl ? g4.w : g4.x;  G[1] = oddl ? g4.z : g4.y;
      G[2] = oddl ? g4.y : g4.z;  G[3] = oddl ? g4.x : g4.w;
      B[0] = oddl ? b4.w : b4.x;  B[1] = oddl ? b4.z : b4.y;
      B[2] = oddl ? b4.y : b4.z;  B[3] = oddl ? b4.x : b4.w;

      int s = row * 64 + swzc(c4);

      float ch[4];
#pragma unroll
      for (int q = 0; q < 4; ++q)   // Y ((x+1)/2*255 folded in)
        ch[q] = fmaf(38.1225f, R[q], fmaf(74.8425f, G[q], fmaf(14.535f, B[q], 127.5f)));
      half_dct(ch, cf, sgn);
      *(float4*)&sm[s] = make_float4(ch[0], ch[1], ch[2], ch[3]);

#pragma unroll
      for (int q = 0; q < 4; ++q)   // Cb
        ch[q] = fmaf(-21.51384f, R[q], fmaf(-42.23616f, G[q], fmaf(63.75f, B[q], 128.f)));
      half_dct(ch, cf, sgn);
      *(float4*)&sm[PL + s] = make_float4(ch[0], ch[1], ch[2], ch[3]);

#pragma unroll
      for (int q = 0; q < 4; ++q)   // Cr
        ch[q] = fmaf(63.75f, R[q], fmaf(-53.38272f, G[q], fmaf(-10.36728f, B[q], 128.f)));
      half_dct(ch, cf, sgn);
      *(float4*)&sm[2 * PL + s] = make_float4(ch[0], ch[1], ch[2], ch[3]);
    }
  }
  __syncthreads();

  // --- Phase 2: col DCT + diff-round quant + col IDCT (1 vector per channel) ---
  {
    const int colb = tid & 63;
    const int slot = colb & 7;          // permuted freq slot
    const int brb = tid >> 6;           // 0..3
    const int base0 = brb * 512 + swzc(colb);
    float qa[8], qb[8];
#pragma unroll
    for (int k = 0; k < 3; ++k) {
      if (k < 2) {                      // k=2 (Cr) reuses C tables from k=1
        const int koff = k ? 64 : 0;
#pragma unroll
        for (int u = 0; u < 8; ++u) {
          qa[u] = sQA[koff + slot + u * 8];
          qb[u] = sQB[koff + slot + u * 8];
        }
      }
      int base = k * PL + base0;
      float vec[8];
#pragma unroll
      for (int r = 0; r < 8; ++r) vec[r] = sm[base + r * 64];
      dct1(vec);
      if (slot == 0) vec[0] -= 8192.f;  // DC offset == (p-128) pre-DCT
#pragma unroll
      for (int u = 0; u < 8; ++u) {
        float s = vec[u] * qa[u];
        float r = rintf(s);             // half-to-even == jnp.round
        float d = s - r;
        vec[u] = fmaf(d * d, d, r) * qb[u];
      }
      idct1(vec);
#pragma unroll
      for (int r = 0; r < 8; ++r) sm[base + r * 64] = vec[r];
    }
  }
  __syncthreads();

  // ------- Phase 3: smem -> half row-IDCT -> YCbCr->RGB -> gmem -------
  {
    float ci[16];
    const float* cip = CI + (oddl ? 16 : 0);
#pragma unroll
    for (int t = 0; t < 16; ++t) ci[t] = cip[t];

    float* __restrict__ qr = out + img;
    float* __restrict__ qg = out + img + plane;
    float* __restrict__ qb2 = out + img + 2 * plane;

#pragma unroll
    for (int it = 0; it < 2; ++it) {
      int i = tid + it * 256;
      int row = i >> 4;
      int c4 = (i & 15) << 2;
      int s = row * 64 + swzc(c4);

      float y[4], cb[4], cr[4];
      float4 t4;
      t4 = *(const float4*)&sm[s];
      y[0]=t4.x; y[1]=t4.y; y[2]=t4.z; y[3]=t4.w;
      half_idct(y, ci, sgn);
      t4 = *(const float4*)&sm[PL + s];
      cb[0]=t4.x; cb[1]=t4.y; cb[2]=t4.z; cb[3]=t4.w;
      half_idct(cb, ci, sgn);
      t4 = *(const float4*)&sm[2 * PL + s];
      cr[0]=t4.x; cr[1]=t4.y; cr[2]=t4.z; cr[3]=t4.w;
      half_idct(cr, ci, sgn);

      // color transform per pixel (order-independent), then un-reverse at store
      float R[4], G[4], B[4];
#pragma unroll
      for (int q = 0; q < 4; ++q) {
        float y128 = y[q] + 128.f;      // recon is centered (DC trick)
        float r = fmaf(1.402f, cr[q], y128);
        float gg = fmaf(-0.714136f, cr[q], fmaf(-0.344136f, cb[q], y128));
        float b = fmaf(1.772f, cb[q], y128);
        const float inv255 = 1.0f / 255.0f;
        R[q] = fminf(fmaxf(r, 0.f), 255.f) * inv255;
        G[q] = fminf(fmaxf(gg, 0.f), 255.f) * inv255;
        B[q] = fminf(fmaxf(b, 0.f), 255.f) * inv255;
      }
      size_t g = (size_t)(gy0 + row) * Ww + (gx0 + c4);
      float4 ro = oddl ? make_float4(R[3], R[2], R[1], R[0]) : make_float4(R[0], R[1], R[2], R[3]);
      float4 go = oddl ? make_float4(G[3], G[2], G[1], G[0]) : make_float4(G[0], G[1], G[2], G[3]);
      float4 bo = oddl ? make_float4(B[3], B[2], B[1], B[0]) : make_float4(B[0], B[1], B[2], B[3]);
      *(float4*)(qr + g)  = ro;
      *(float4*)(qg + g)  = go;
      *(float4*)(qb2 + g) = bo;
    }
  }
}

} // namespace

extern "C" void kernel_launch(void* const* d_in, const int* in_sizes, int n_in,
                              void* d_out, int out_size) {
  (void)in_sizes; (void)n_in; (void)out_size;
  const float* in = (const float*)d_in[0];
  float* out = (float*)d_out;
  constexpr int SMEM = (3 * PL + 256) * 4;   // 25600 bytes
  static bool attr_set = false;
  if (!attr_set) {
    cudaFuncSetAttribute(jpeg_kernel, cudaFuncAttributeMaxDynamicSharedMemorySize, SMEM);
    attr_set = true;
  }
  dim3 grid(Ww / TW, Hh / TH, 16);
  jpeg_kernel<<<grid, 256, SMEM>>>(in, out);
}

// round 8
// speedup vs baseline: 1.0548x; 1.0548x over previous
#include <cuda_runtime.h>

// JPEG compress/decompress (DiffJPEG, factor=1.0) for [16,3,512,512] fp32 in [-1,1].
// One CTA = one 64x32 tile, 256 threads, 4 CTAs/SM.
// Phase 1: gmem -> YCbCr -> lane-pair half row-DCT -> smem (permuted freq slots)
// Phase 2: VECTORIZED column pass: each thread owns 4 adjacent columns (float4
//          per row, conflict-free under the swizzle): col DCT + diff-round
//          quant + col IDCT. Quant tables are slot-permuted so the 4 columns'
//          coefficients form one aligned float4.
// Phase 3: smem -> lane-pair half row-IDCT -> YCbCr->RGB -> gmem
// DC trick: subtract 128*64 from the DC coefficient; re-add 128 at output.

namespace {

constexpr int Hh = 512;
constexpr int Ww = 512;
constexpr int TW = 64;
constexpr int TH = 32;
constexpr int PL = TW * TH;   // 2048 floats per channel plane

// Forward half-transform coefs: CF[p][m][k] = Dm[2m+p][k], k=0..3
__constant__ float CF[32] = {
  1.f,          1.f,          1.f,          1.f,
  0.92387953f,  0.38268343f, -0.38268343f, -0.92387953f,
  0.70710678f, -0.70710678f, -0.70710678f,  0.70710678f,
  0.38268343f, -0.92387953f,  0.92387953f, -0.38268343f,
  0.98078528f,  0.83146961f,  0.55557023f,  0.19509032f,
  0.83146961f, -0.19509032f, -0.98078528f, -0.55557023f,
  0.55557023f, -0.98078528f,  0.19509032f,  0.83146961f,
  0.19509032f, -0.55557023f,  0.83146961f, -0.98078528f,
};
// Inverse half-transform coefs: CI[p][k][m] = Dm[2m+p][k]
__constant__ float CI[32] = {
  1.f,  0.92387953f,  0.70710678f,  0.38268343f,
  1.f,  0.38268343f, -0.70710678f, -0.92387953f,
  1.f, -0.38268343f, -0.70710678f,  0.92387953f,
  1.f, -0.92387953f,  0.70710678f, -0.38268343f,
  0.98078528f,  0.83146961f,  0.55557023f,  0.19509032f,
  0.83146961f, -0.19509032f, -0.98078528f, -0.55557023f,
  0.55557023f, -0.98078528f,  0.19509032f,  0.83146961f,
  0.19509032f, -0.55557023f,  0.83146961f, -0.98078528f,
};

// Full 8-point DCT basis for the column pass
__device__ static constexpr float Dm[8][8] = {
  { 1.f,          1.f,          1.f,          1.f,          1.f,          1.f,          1.f,          1.f         },
  { 0.98078528f,  0.83146961f,  0.55557023f,  0.19509032f, -0.19509032f, -0.55557023f, -0.83146961f, -0.98078528f },
  { 0.92387953f,  0.38268343f, -0.38268343f, -0.92387953f, -0.92387953f, -0.38268343f,  0.38268343f,  0.92387953f },
  { 0.83146961f, -0.19509032f, -0.98078528f, -0.55557023f,  0.55557023f,  0.98078528f,  0.19509032f, -0.83146961f },
  { 0.70710678f, -0.70710678f, -0.70710678f,  0.70710678f,  0.70710678f, -0.70710678f, -0.70710678f,  0.70710678f },
  { 0.55557023f, -0.98078528f,  0.19509032f,  0.83146961f, -0.83146961f, -0.19509032f,  0.98078528f, -0.55557023f },
  { 0.38268343f, -0.92387953f,  0.92387953f, -0.38268343f, -0.38268343f,  0.92387953f, -0.92387953f,  0.38268343f },
  { 0.19509032f, -0.55557023f,  0.83146961f, -0.98078528f,  0.98078528f, -0.83146961f,  0.55557023f, -0.19509032f },
};

__device__ static const float QY[64] = {
  16, 11, 10, 16, 24, 40, 51, 61,
  12, 12, 14, 19, 26, 58, 60, 55,
  14, 13, 16, 24, 40, 57, 69, 56,
  14, 17, 22, 29, 51, 87, 80, 62,
  18, 22, 37, 56, 68, 109, 103, 77,
  24, 35, 55, 64, 81, 104, 113, 92,
  49, 64, 78, 87, 103, 121, 120, 101,
  72, 92, 95, 98, 112, 100, 103, 99
};
__device__ static const float QC[64] = {
  17, 18, 24, 47, 99, 99, 99, 99,
  18, 21, 26, 66, 99, 99, 99, 99,
  24, 26, 56, 99, 99, 99, 99, 99,
  47, 66, 99, 99, 99, 99, 99, 99,
  99, 99, 99, 99, 99, 99, 99, 99,
  99, 99, 99, 99, 99, 99, 99, 99,
  99, 99, 99, 99, 99, 99, 99, 99,
  99, 99, 99, 99, 99, 99, 99, 99
};

__device__ __forceinline__ int swzc(int c) { return c ^ ((c & 32) >> 3); }

__device__ __forceinline__ void dct1(float* v) {
  float e0 = v[0] + v[7], e1 = v[1] + v[6], e2 = v[2] + v[5], e3 = v[3] + v[4];
  float o0 = v[0] - v[7], o1 = v[1] - v[6], o2 = v[2] - v[5], o3 = v[3] - v[4];
  v[0] = (e0 + e3) + (e1 + e2);
  v[4] = Dm[4][0] * ((e0 + e3) - (e1 + e2));
  v[2] = Dm[2][0]*e0 + Dm[2][1]*e1 + Dm[2][2]*e2 + Dm[2][3]*e3;
  v[6] = Dm[6][0]*e0 + Dm[6][1]*e1 + Dm[6][2]*e2 + Dm[6][3]*e3;
  v[1] = Dm[1][0]*o0 + Dm[1][1]*o1 + Dm[1][2]*o2 + Dm[1][3]*o3;
  v[3] = Dm[3][0]*o0 + Dm[3][1]*o1 + Dm[3][2]*o2 + Dm[3][3]*o3;
  v[5] = Dm[5][0]*o0 + Dm[5][1]*o1 + Dm[5][2]*o2 + Dm[5][3]*o3;
  v[7] = Dm[7][0]*o0 + Dm[7][1]*o1 + Dm[7][2]*o2 + Dm[7][3]*o3;
}
__device__ __forceinline__ void idct1(float* v) {
  float i0 = v[0], i1 = v[1], i2 = v[2], i3 = v[3];
  float i4 = v[4], i5 = v[5], i6 = v[6], i7 = v[7];
#pragma unroll
  for (int k = 0; k < 4; ++k) {
    float ev = i0 + Dm[2][k]*i2 + Dm[4][k]*i4 + Dm[6][k]*i6;
    float od = Dm[1][k]*i1 + Dm[3][k]*i3 + Dm[5][k]*i5 + Dm[7][k]*i7;
    v[k]     = ev + od;
    v[7 - k] = ev - od;
  }
}

// Lane-pair half row-DCT (even lane: natural px, odd lane: reversed px)
__device__ __forceinline__ void half_dct(float v[4], const float cf[16], float sgn) {
  float t0 = __shfl_xor_sync(0xffffffffu, v[0], 1);
  float t1 = __shfl_xor_sync(0xffffffffu, v[1], 1);
  float t2 = __shfl_xor_sync(0xffffffffu, v[2], 1);
  float t3 = __shfl_xor_sync(0xffffffffu, v[3], 1);
  float x0 = fmaf(sgn, v[0], t0);
  float x1 = fmaf(sgn, v[1], t1);
  float x2 = fmaf(sgn, v[2], t2);
  float x3 = fmaf(sgn, v[3], t3);
  v[0] = fmaf(cf[3],  x3, fmaf(cf[2],  x2, fmaf(cf[1],  x1, cf[0]  * x0)));
  v[1] = fmaf(cf[7],  x3, fmaf(cf[6],  x2, fmaf(cf[5],  x1, cf[4]  * x0)));
  v[2] = fmaf(cf[11], x3, fmaf(cf[10], x2, fmaf(cf[9],  x1, cf[8]  * x0)));
  v[3] = fmaf(cf[15], x3, fmaf(cf[14], x2, fmaf(cf[13], x1, cf[12] * x0)));
}

// Lane-pair half row-IDCT (even lane out: natural px, odd lane out: reversed px)
__device__ __forceinline__ void half_idct(float f[4], const float ci[16], float sgn) {
  float g0 = fmaf(ci[3],  f[3], fmaf(ci[2],  f[2], fmaf(ci[1],  f[1], ci[0]  * f[0])));
  float g1 = fmaf(ci[7],  f[3], fmaf(ci[6],  f[2], fmaf(ci[5],  f[1], ci[4]  * f[0])));
  float g2 = fmaf(ci[11], f[3], fmaf(ci[10], f[2], fmaf(ci[9],  f[1], ci[8]  * f[0])));
  float g3 = fmaf(ci[15], f[3], fmaf(ci[14], f[2], fmaf(ci[13], f[1], ci[12] * f[0])));
  float t0 = __shfl_xor_sync(0xffffffffu, g0, 1);
  float t1 = __shfl_xor_sync(0xffffffffu, g1, 1);
  float t2 = __shfl_xor_sync(0xffffffffu, g2, 1);
  float t3 = __shfl_xor_sync(0xffffffffu, g3, 1);
  f[0] = fmaf(sgn, g0, t0);
  f[1] = fmaf(sgn, g1, t1);
  f[2] = fmaf(sgn, g2, t2);
  f[3] = fmaf(sgn, g3, t3);
}

__global__ void __launch_bounds__(256, 4)
jpeg_kernel(const float* __restrict__ in, float* __restrict__ out) {
  extern __shared__ float sm[];         // 3*2048 planes + 128 SA + 128 SB
  float* sQA = sm + 3 * PL;             // slot-permuted: 0.25*au*av / Q
  float* sQB = sm + 3 * PL + 128;       // slot-permuted: 0.25*au*av * Q

  const int tid = threadIdx.x;
  const bool oddl = (tid & 1) != 0;
  const float sgn = oddl ? -1.f : 1.f;
  const int gx0 = blockIdx.x * TW;
  const int gy0 = blockIdx.y * TH;
  const size_t plane = (size_t)Hh * Ww;
  const size_t img = (size_t)blockIdx.z * 3 * plane;
  const float* __restrict__ pr = in + img;
  const float* __restrict__ pg = in + img + plane;
  const float* __restrict__ pb = in + img + 2 * plane;

  // ---- quant table fill (slot s holds freq perm[s] = {0,2,4,6,1,3,5,7}) ----
  if (tid < 128) {
    int tab = tid >> 6, uv = tid & 63, u = uv >> 3, s = uv & 7;
    int v = (s < 4) ? (s << 1) : ((s << 1) - 7);
    float a = 0.25f * (u ? 1.f : 0.70710678118654752f)
                    * (v ? 1.f : 0.70710678118654752f);
    float Q = tab ? QC[u * 8 + v] : QY[u * 8 + v];
    sQA[tid] = a / Q;
    sQB[tid] = a * Q;
  }

  // ------- Phase 1: gmem -> YCbCr -> half row-DCT -> smem (channel-serial) -------
  {
    float cf[16];
    const float* cfp = CF + (oddl ? 16 : 0);
#pragma unroll
    for (int t = 0; t < 16; ++t) cf[t] = cfp[t];

#pragma unroll
    for (int it = 0; it < 2; ++it) {
      int i = tid + it * 256;
      int row = i >> 4;                 // 0..31
      int c4 = (i & 15) << 2;
      size_t g = (size_t)(gy0 + row) * Ww + (gx0 + c4);
      float4 r4 = *(const float4*)(pr + g);
      float4 g4 = *(const float4*)(pg + g);
      float4 b4 = *(const float4*)(pb + g);

      // odd lanes reverse their 4 pixels (pixel order 8j+7..8j+4)
      float R[4], G[4], B[4];
      R[0] = oddl ? r4.w : r4.x;  R[1] = oddl ? r4.z : r4.y;
      R[2] = oddl ? r4.y : r4.z;  R[3] = oddl ? r4.x : r4.w;
      G[0] = oddl ? g4.w : g4.x;  G[1] = oddl ? g4.z : g4.y;
      G[2] = oddl ? g4.y : g4.z;  G[3] = oddl ? g4.x : g4.w;
      B[0] = oddl ? b4.w : b4.x;  B[1] = oddl ? b4.z : b4.y;
      B[2] = oddl ? b4.y : b4.z;  B[3] = oddl ? b4.x : b4.w;

      int s = row * 64 + swzc(c4);

      float ch[4];
#pragma unroll
      for (int q = 0; q < 4; ++q)   // Y ((x+1)/2*255 folded in)
        ch[q] = fmaf(38.1225f, R[q], fmaf(74.8425f, G[q], fmaf(14.535f, B[q], 127.5f)));
      half_dct(ch, cf, sgn);
      *(float4*)&sm[s] = make_float4(ch[0], ch[1], ch[2], ch[3]);

#pragma unroll
      for (int q = 0; q < 4; ++q)   // Cb
        ch[q] = fmaf(-21.51384f, R[q], fmaf(-42.23616f, G[q], fmaf(63.75f, B[q], 128.f)));
      half_dct(ch, cf, sgn);
      *(float4*)&sm[PL + s] = make_float4(ch[0], ch[1], ch[2], ch[3]);

#pragma unroll
      for (int q = 0; q < 4; ++q)   // Cr
        ch[q] = fmaf(63.75f, R[q], fmaf(-53.38272f, G[q], fmaf(-10.36728f, B[q], 128.f)));
      half_dct(ch, cf, sgn);
      *(float4*)&sm[2 * PL + s] = make_float4(ch[0], ch[1], ch[2], ch[3]);
    }
  }
  __syncthreads();

  // --- Phase 2: vectorized column pass, 4 adjacent columns per thread ---
  // 192 active threads: k = tid>>6 (channel), colgroup = tid&15, blockrow = (tid>>4)&3.
  // float4 per row: same r across all lanes -> conflict-free LDS.128/STS.128.
  if (tid < 192) {
    const int k = tid >> 6;
    const int idx = tid & 63;
    const int cg = idx & 15;
    const int br = idx >> 4;            // 0..3
    const int c4 = cg << 2;
    const int slot0 = c4 & 7;           // 0 or 4 (permuted freq slot of elem .x)
    const int koff = k ? 64 : 0;
    const int base = k * PL + br * 512 + swzc(c4);

    float va[8], vb[8], vc[8], vd[8];
#pragma unroll
    for (int r = 0; r < 8; ++r) {
      float4 t = *(const float4*)&sm[base + r * 64];
      va[r] = t.x; vb[r] = t.y; vc[r] = t.z; vd[r] = t.w;
    }
    dct1(va); dct1(vb); dct1(vc); dct1(vd);
    if (slot0 == 0) va[0] -= 8192.f;    // DC offset == (p-128) pre-DCT

#pragma unroll
    for (int u = 0; u < 8; ++u) {
      float4 qa = *(const float4*)&sQA[koff + u * 8 + slot0];
      float4 qb = *(const float4*)&sQB[koff + u * 8 + slot0];
      float s0 = va[u] * qa.x, r0 = rintf(s0), d0 = s0 - r0;
      va[u] = fmaf(d0 * d0, d0, r0) * qb.x;
      float s1 = vb[u] * qa.y, r1 = rintf(s1), d1 = s1 - r1;
      vb[u] = fmaf(d1 * d1, d1, r1) * qb.y;
      float s2 = vc[u] * qa.z, r2 = rintf(s2), d2 = s2 - r2;
      vc[u] = fmaf(d2 * d2, d2, r2) * qb.z;
      float s3 = vd[u] * qa.w, r3 = rintf(s3), d3 = s3 - r3;
      vd[u] = fmaf(d3 * d3, d3, r3) * qb.w;
    }

    idct1(va); idct1(vb); idct1(vc); idct1(vd);
#pragma unroll
    for (int r = 0; r < 8; ++r)
      *(float4*)&sm[base + r * 64] = make_float4(va[r], vb[r], vc[r], vd[r]);
  }
  __syncthreads();

  // ------- Phase 3: smem -> half row-IDCT -> YCbCr->RGB -> gmem -------
  {
    float ci[16];
    const float* cip = CI + (oddl ? 16 : 0);
#pragma unroll
    for (int t = 0; t < 16; ++t) ci[t] = cip[t];

    float* __restrict__ qr = out + img;
    float* __restrict__ qg = out + img + plane;
    float* __restrict__ qb2 = out + img + 2 * plane;

#pragma unroll
    for (int it = 0; it < 2; ++it) {
      int i = tid + it * 256;
      int row = i >> 4;
      int c4 = (i & 15) << 2;
      int s = row * 64 + swzc(c4);

      float y[4], cb[4], cr[4];
      float4 t4;
      t4 = *(const float4*)&sm[s];
      y[0]=t4.x; y[1]=t4.y; y[2]=t4.z; y[3]=t4.w;
      half_idct(y, ci, sgn);
      t4 = *(const float4*)&sm[PL + s];
      cb[0]=t4.x; cb[1]=t4.y; cb[2]=t4.z; cb[3]=t4.w;
      half_idct(cb, ci, sgn);
      t4 = *(const float4*)&sm[2 * PL + s];
      cr[0]=t4.x; cr[1]=t4.y; cr[2]=t4.z; cr[3]=t4.w;
      half_idct(cr, ci, sgn);

      float R[4], G[4], B[4];
#pragma unroll
      for (int q = 0; q < 4; ++q) {
        float y128 = y[q] + 128.f;      // recon is centered (DC trick)
        float r = fmaf(1.402f, cr[q], y128);
        float gg = fmaf(-0.714136f, cr[q], fmaf(-0.344136f, cb[q], y128));
        float b = fmaf(1.772f, cb[q], y128);
        const float inv255 = 1.0f / 255.0f;
        R[q] = fminf(fmaxf(r, 0.f), 255.f) * inv255;
        G[q] = fminf(fmaxf(gg, 0.f), 255.f) * inv255;
        B[q] = fminf(fmaxf(b, 0.f), 255.f) * inv255;
      }
      size_t g = (size_t)(gy0 + row) * Ww + (gx0 + c4);
      float4 ro = oddl ? make_float4(R[3], R[2], R[1], R[0]) : make_float4(R[0], R[1], R[2], R[3]);
      float4 go = oddl ? make_float4(G[3], G[2], G[1], G[0]) : make_float4(G[0], G[1], G[2], G[3]);
      float4 bo = oddl ? make_float4(B[3], B[2], B[1], B[0]) : make_float4(B[0], B[1], B[2], B[3]);
      *(float4*)(qr + g)  = ro;
      *(float4*)(qg + g)  = go;
      *(float4*)(qb2 + g) = bo;
    }
  }
}

} // namespace

extern "C" void kernel_launch(void* const* d_in, const int* in_sizes, int n_in,
                              void* d_out, int out_size) {
  (void)in_sizes; (void)n_in; (void)out_size;
  const float* in = (const float*)d_in[0];
  float* out = (float*)d_out;
  constexpr int SMEM = (3 * PL + 256) * 4;   // 25600 bytes
  static bool attr_set = false;
  if (!attr_set) {
    cudaFuncSetAttribute(jpeg_kernel, cudaFuncAttributeMaxDynamicSharedMemorySize, SMEM);
    attr_set = true;
  }
  dim3 grid(Ww / TW, Hh / TH, 16);
  jpeg_kernel<<<grid, 256, SMEM>>>(in, out);
}

// round 9
// speedup vs baseline: 1.1356x; 1.0767x over previous
#include <cuda_runtime.h>

// JPEG compress/decompress (DiffJPEG, factor=1.0) for [16,3,512,512] fp32 in [-1,1].
// One CTA = one 64x32 tile, 256 threads, 4 CTAs/SM.
// Phase 1: gmem -> YCbCr -> lane-pair half row-DCT -> smem (permuted freq slots)
// Phase 2: PACKED f32x2 column pass: each thread owns 4 adjacent columns,
//          processed as two f32x2 pairs (a,b) and (c,d): col DCT + diff-round
//          quant (magic-constant RNE round) + col IDCT, all in fma.rn.f32x2.
// Phase 3: smem -> lane-pair half row-IDCT -> YCbCr->RGB -> gmem
// DC trick: subtract 128*64 from the DC coefficient; re-add 128 at output.

namespace {

constexpr int Hh = 512;
constexpr int Ww = 512;
constexpr int TW = 64;
constexpr int TH = 32;
constexpr int PL = TW * TH;   // 2048 floats per channel plane

typedef unsigned long long u64;

__device__ __forceinline__ u64 F2PK(float a, float b) {
  u64 r; asm("mov.b64 %0,{%1,%2};" : "=l"(r) : "f"(a), "f"(b)); return r;
}
__device__ __forceinline__ u64 FMA2(u64 a, u64 b, u64 c) {
  u64 d; asm("fma.rn.f32x2 %0,%1,%2,%3;" : "=l"(d) : "l"(a), "l"(b), "l"(c)); return d;
}
__device__ __forceinline__ u64 ADD2(u64 a, u64 b) {
  u64 d; asm("add.rn.f32x2 %0,%1,%2;" : "=l"(d) : "l"(a), "l"(b)); return d;
}
__device__ __forceinline__ u64 MUL2(u64 a, u64 b) {
  u64 d; asm("mul.rn.f32x2 %0,%1,%2;" : "=l"(d) : "l"(a), "l"(b)); return d;
}

// Forward half-transform coefs: CF[p][m][k] = Dm[2m+p][k], k=0..3
__constant__ float CF[32] = {
  1.f,          1.f,          1.f,          1.f,
  0.92387953f,  0.38268343f, -0.38268343f, -0.92387953f,
  0.70710678f, -0.70710678f, -0.70710678f,  0.70710678f,
  0.38268343f, -0.92387953f,  0.92387953f, -0.38268343f,
  0.98078528f,  0.83146961f,  0.55557023f,  0.19509032f,
  0.83146961f, -0.19509032f, -0.98078528f, -0.55557023f,
  0.55557023f, -0.98078528f,  0.19509032f,  0.83146961f,
  0.19509032f, -0.55557023f,  0.83146961f, -0.98078528f,
};
// Inverse half-transform coefs: CI[p][k][m] = Dm[2m+p][k]
__constant__ float CI[32] = {
  1.f,  0.92387953f,  0.70710678f,  0.38268343f,
  1.f,  0.38268343f, -0.70710678f, -0.92387953f,
  1.f, -0.38268343f, -0.70710678f,  0.92387953f,
  1.f, -0.92387953f,  0.70710678f, -0.38268343f,
  0.98078528f,  0.83146961f,  0.55557023f,  0.19509032f,
  0.83146961f, -0.19509032f, -0.98078528f, -0.55557023f,
  0.55557023f, -0.98078528f,  0.19509032f,  0.83146961f,
  0.19509032f, -0.55557023f,  0.83146961f, -0.98078528f,
};

__device__ static const float QY[64] = {
  16, 11, 10, 16, 24, 40, 51, 61,
  12, 12, 14, 19, 26, 58, 60, 55,
  14, 13, 16, 24, 40, 57, 69, 56,
  14, 17, 22, 29, 51, 87, 80, 62,
  18, 22, 37, 56, 68, 109, 103, 77,
  24, 35, 55, 64, 81, 104, 113, 92,
  49, 64, 78, 87, 103, 121, 120, 101,
  72, 92, 95, 98, 112, 100, 103, 99
};
__device__ static const float QC[64] = {
  17, 18, 24, 47, 99, 99, 99, 99,
  18, 21, 26, 66, 99, 99, 99, 99,
  24, 26, 56, 99, 99, 99, 99, 99,
  47, 66, 99, 99, 99, 99, 99, 99,
  99, 99, 99, 99, 99, 99, 99, 99,
  99, 99, 99, 99, 99, 99, 99, 99,
  99, 99, 99, 99, 99, 99, 99, 99,
  99, 99, 99, 99, 99, 99, 99, 99
};

__device__ __forceinline__ int swzc(int c) { return c ^ ((c & 32) >> 3); }

// Packed-constant indices
enum { C_NEG1 = 0, C_C4, C_C2, C_C6, C_C2N, C_C1, C_C1N, C_C3, C_C5, C_C5N, C_C7, C_C7N, C_NUM };

// Packed 8-point DCT-II on f32x2 vector (two independent columns per lane half)
__device__ __forceinline__ void dct2(u64* v, const u64* C) {
  u64 e0 = ADD2(v[0], v[7]), e1 = ADD2(v[1], v[6]);
  u64 e2 = ADD2(v[2], v[5]), e3 = ADD2(v[3], v[4]);
  u64 o0 = FMA2(v[7], C[C_NEG1], v[0]), o1 = FMA2(v[6], C[C_NEG1], v[1]);
  u64 o2 = FMA2(v[5], C[C_NEG1], v[2]), o3 = FMA2(v[4], C[C_NEG1], v[3]);
  u64 s03 = ADD2(e0, e3), s12 = ADD2(e1, e2);
  v[0] = ADD2(s03, s12);
  v[4] = MUL2(C[C_C4], FMA2(s12, C[C_NEG1], s03));
  u64 d03 = FMA2(e3, C[C_NEG1], e0), d12 = FMA2(e2, C[C_NEG1], e1);
  v[2] = FMA2(C[C_C6], d12, MUL2(C[C_C2], d03));
  v[6] = FMA2(C[C_C2N], d12, MUL2(C[C_C6], d03));
  v[1] = FMA2(C[C_C7],  o3, FMA2(C[C_C5],  o2, FMA2(C[C_C3],  o1, MUL2(C[C_C1], o0))));
  v[3] = FMA2(C[C_C5N], o3, FMA2(C[C_C1N], o2, FMA2(C[C_C7N], o1, MUL2(C[C_C3], o0))));
  v[5] = FMA2(C[C_C3],  o3, FMA2(C[C_C7],  o2, FMA2(C[C_C1N], o1, MUL2(C[C_C5], o0))));
  v[7] = FMA2(C[C_C1N], o3, FMA2(C[C_C3],  o2, FMA2(C[C_C5N], o1, MUL2(C[C_C7], o0))));
}

// Packed 8-point IDCT (alpha already folded into tables)
__device__ __forceinline__ void idct2(u64* v, const u64* C) {
  u64 t = MUL2(C[C_C4], v[4]);
  u64 p = ADD2(v[0], t);
  u64 m = FMA2(t, C[C_NEG1], v[0]);
  u64 u1 = FMA2(C[C_C6], v[6], MUL2(C[C_C2], v[2]));
  u64 u2 = FMA2(C[C_C2N], v[6], MUL2(C[C_C6], v[2]));
  u64 ev0 = ADD2(p, u1), ev3 = FMA2(u1, C[C_NEG1], p);
  u64 ev1 = ADD2(m, u2), ev2 = FMA2(u2, C[C_NEG1], m);
  u64 i1 = v[1], i3 = v[3], i5 = v[5], i7 = v[7];
  u64 od0 = FMA2(C[C_C7],  i7, FMA2(C[C_C5],  i5, FMA2(C[C_C3],  i3, MUL2(C[C_C1], i1))));
  u64 od1 = FMA2(C[C_C5N], i7, FMA2(C[C_C1N], i5, FMA2(C[C_C7N], i3, MUL2(C[C_C3], i1))));
  u64 od2 = FMA2(C[C_C3],  i7, FMA2(C[C_C7],  i5, FMA2(C[C_C1N], i3, MUL2(C[C_C5], i1))));
  u64 od3 = FMA2(C[C_C1N], i7, FMA2(C[C_C3],  i5, FMA2(C[C_C5N], i3, MUL2(C[C_C7], i1))));
  v[0] = ADD2(ev0, od0);  v[7] = FMA2(od0, C[C_NEG1], ev0);
  v[1] = ADD2(ev1, od1);  v[6] = FMA2(od1, C[C_NEG1], ev1);
  v[2] = ADD2(ev2, od2);  v[5] = FMA2(od2, C[C_NEG1], ev2);
  v[3] = ADD2(ev3, od3);  v[4] = FMA2(od3, C[C_NEG1], ev3);
}

// Lane-pair half row-DCT (even lane: natural px, odd lane: reversed px)
__device__ __forceinline__ void half_dct(float v[4], const float cf[16], float sgn) {
  float t0 = __shfl_xor_sync(0xffffffffu, v[0], 1);
  float t1 = __shfl_xor_sync(0xffffffffu, v[1], 1);
  float t2 = __shfl_xor_sync(0xffffffffu, v[2], 1);
  float t3 = __shfl_xor_sync(0xffffffffu, v[3], 1);
  float x0 = fmaf(sgn, v[0], t0);
  float x1 = fmaf(sgn, v[1], t1);
  float x2 = fmaf(sgn, v[2], t2);
  float x3 = fmaf(sgn, v[3], t3);
  v[0] = fmaf(cf[3],  x3, fmaf(cf[2],  x2, fmaf(cf[1],  x1, cf[0]  * x0)));
  v[1] = fmaf(cf[7],  x3, fmaf(cf[6],  x2, fmaf(cf[5],  x1, cf[4]  * x0)));
  v[2] = fmaf(cf[11], x3, fmaf(cf[10], x2, fmaf(cf[9],  x1, cf[8]  * x0)));
  v[3] = fmaf(cf[15], x3, fmaf(cf[14], x2, fmaf(cf[13], x1, cf[12] * x0)));
}

// Lane-pair half row-IDCT (even lane out: natural px, odd lane out: reversed px)
__device__ __forceinline__ void half_idct(float f[4], const float ci[16], float sgn) {
  float g0 = fmaf(ci[3],  f[3], fmaf(ci[2],  f[2], fmaf(ci[1],  f[1], ci[0]  * f[0])));
  float g1 = fmaf(ci[7],  f[3], fmaf(ci[6],  f[2], fmaf(ci[5],  f[1], ci[4]  * f[0])));
  float g2 = fmaf(ci[11], f[3], fmaf(ci[10], f[2], fmaf(ci[9],  f[1], ci[8]  * f[0])));
  float g3 = fmaf(ci[15], f[3], fmaf(ci[14], f[2], fmaf(ci[13], f[1], ci[12] * f[0])));
  float t0 = __shfl_xor_sync(0xffffffffu, g0, 1);
  float t1 = __shfl_xor_sync(0xffffffffu, g1, 1);
  float t2 = __shfl_xor_sync(0xffffffffu, g2, 1);
  float t3 = __shfl_xor_sync(0xffffffffu, g3, 1);
  f[0] = fmaf(sgn, g0, t0);
  f[1] = fmaf(sgn, g1, t1);
  f[2] = fmaf(sgn, g2, t2);
  f[3] = fmaf(sgn, g3, t3);
}

__global__ void __launch_bounds__(256, 4)
jpeg_kernel(const float* __restrict__ in, float* __restrict__ out) {
  extern __shared__ float sm[];         // 3*2048 planes + 128 SA + 128 SB
  float* sQA = sm + 3 * PL;             // slot-permuted: 0.25*au*av / Q
  float* sQB = sm + 3 * PL + 128;       // slot-permuted: 0.25*au*av * Q

  const int tid = threadIdx.x;
  const bool oddl = (tid & 1) != 0;
  const float sgn = oddl ? -1.f : 1.f;
  const int gx0 = blockIdx.x * TW;
  const int gy0 = blockIdx.y * TH;
  const size_t plane = (size_t)Hh * Ww;
  const size_t img = (size_t)blockIdx.z * 3 * plane;
  const float* __restrict__ pr = in + img;
  const float* __restrict__ pg = in + img + plane;
  const float* __restrict__ pb = in + img + 2 * plane;

  // ---- quant table fill (slot s holds freq perm[s] = {0,2,4,6,1,3,5,7}) ----
  if (tid < 128) {
    int tab = tid >> 6, uv = tid & 63, u = uv >> 3, s = uv & 7;
    int v = (s < 4) ? (s << 1) : ((s << 1) - 7);
    float a = 0.25f * (u ? 1.f : 0.70710678118654752f)
                    * (v ? 1.f : 0.70710678118654752f);
    float Q = tab ? QC[u * 8 + v] : QY[u * 8 + v];
    sQA[tid] = a / Q;
    sQB[tid] = a * Q;
  }

  // ------- Phase 1: gmem -> YCbCr -> half row-DCT -> smem (channel-serial) -------
  {
    float cf[16];
    const float* cfp = CF + (oddl ? 16 : 0);
#pragma unroll
    for (int t = 0; t < 16; ++t) cf[t] = cfp[t];

#pragma unroll
    for (int it = 0; it < 2; ++it) {
      int i = tid + it * 256;
      int row = i >> 4;                 // 0..31
      int c4 = (i & 15) << 2;
      size_t g = (size_t)(gy0 + row) * Ww + (gx0 + c4);
      float4 r4 = *(const float4*)(pr + g);
      float4 g4 = *(const float4*)(pg + g);
      float4 b4 = *(const float4*)(pb + g);

      // odd lanes reverse their 4 pixels (pixel order 8j+7..8j+4)
      float R[4], G[4], B[4];
      R[0] = oddl ? r4.w : r4.x;  R[1] = oddl ? r4.z : r4.y;
      R[2] = oddl ? r4.y : r4.z;  R[3] = oddl ? r4.x : r4.w;
      G[0] = oddl ? g4.w : g4.x;  G[1] = oddl ? g4.z : g4.y;
      G[2] = oddl ? g4.y : g4.z;  G[3] = oddl ? g4.x : g4.w;
      B[0] = oddl ? b4.w : b4.x;  B[1] = oddl ? b4.z : b4.y;
      B[2] = oddl ? b4.y : b4.z;  B[3] = oddl ? b4.x : b4.w;

      int s = row * 64 + swzc(c4);

      float ch[4];
#pragma unroll
      for (int q = 0; q < 4; ++q)   // Y ((x+1)/2*255 folded in)
        ch[q] = fmaf(38.1225f, R[q], fmaf(74.8425f, G[q], fmaf(14.535f, B[q], 127.5f)));
      half_dct(ch, cf, sgn);
      *(float4*)&sm[s] = make_float4(ch[0], ch[1], ch[2], ch[3]);

#pragma unroll
      for (int q = 0; q < 4; ++q)   // Cb
        ch[q] = fmaf(-21.51384f, R[q], fmaf(-42.23616f, G[q], fmaf(63.75f, B[q], 128.f)));
      half_dct(ch, cf, sgn);
      *(float4*)&sm[PL + s] = make_float4(ch[0], ch[1], ch[2], ch[3]);

#pragma unroll
      for (int q = 0; q < 4; ++q)   // Cr
        ch[q] = fmaf(63.75f, R[q], fmaf(-53.38272f, G[q], fmaf(-10.36728f, B[q], 128.f)));
      half_dct(ch, cf, sgn);
      *(float4*)&sm[2 * PL + s] = make_float4(ch[0], ch[1], ch[2], ch[3]);
    }
  }
  __syncthreads();

  // --- Phase 2: packed f32x2 column pass, 4 adjacent columns per thread ---
  // 192 active threads; two passes over pairs (a,b) and (c,d). All data stays
  // packed from LDS.64 to STS.64; arithmetic in fma/add/mul.rn.f32x2.
  if (tid < 192) {
    const int k = tid >> 6;
    const int idx = tid & 63;
    const int cg = idx & 15;
    const int br = idx >> 4;            // 0..3
    const int c4i = cg << 2;
    const int slot0 = c4i & 7;          // 0 or 4 (permuted freq slot of elem .x)
    const int koff = k ? 64 : 0;
    const int base = k * PL + br * 512 + swzc(c4i);

    u64 C[C_NUM];
    C[C_NEG1] = F2PK(-1.f, -1.f);
    C[C_C4]   = F2PK(0.70710678f, 0.70710678f);
    C[C_C2]   = F2PK(0.92387953f, 0.92387953f);
    C[C_C6]   = F2PK(0.38268343f, 0.38268343f);
    C[C_C2N]  = F2PK(-0.92387953f, -0.92387953f);
    C[C_C1]   = F2PK(0.98078528f, 0.98078528f);
    C[C_C1N]  = F2PK(-0.98078528f, -0.98078528f);
    C[C_C3]   = F2PK(0.83146961f, 0.83146961f);
    C[C_C5]   = F2PK(0.55557023f, 0.55557023f);
    C[C_C5N]  = F2PK(-0.55557023f, -0.55557023f);
    C[C_C7]   = F2PK(0.19509032f, 0.19509032f);
    C[C_C7N]  = F2PK(-0.19509032f, -0.19509032f);
    const u64 MAG = F2PK(12582912.f, 12582912.f);   // 1.5*2^23 (RNE magic)
    const u64 DCC = F2PK(-8192.f, 0.f);             // DC offset, lo half only

#pragma unroll
    for (int pass = 0; pass < 2; ++pass) {
      const int off = pass * 2;
      u64 v[8];
#pragma unroll
      for (int r = 0; r < 8; ++r)
        v[r] = *(const u64*)&sm[base + r * 64 + off];
      dct2(v, C);
      if (pass == 0 && slot0 == 0) v[0] = ADD2(v[0], DCC);
#pragma unroll
      for (int u = 0; u < 8; ++u) {
        u64 qa2 = *(const u64*)&sQA[koff + u * 8 + slot0 + off];
        u64 qb2 = *(const u64*)&sQB[koff + u * 8 + slot0 + off];
        u64 s = MUL2(v[u], qa2);
        u64 r = FMA2(MAG, C[C_NEG1], ADD2(s, MAG));  // RNE round
        u64 d = FMA2(r, C[C_NEG1], s);
        u64 q = FMA2(MUL2(d, d), d, r);              // diff_round
        v[u] = MUL2(q, qb2);
      }
      idct2(v, C);
#pragma unroll
      for (int r = 0; r < 8; ++r)
        *(u64*)&sm[base + r * 64 + off] = v[r];
    }
  }
  __syncthreads();

  // ------- Phase 3: smem -> half row-IDCT -> YCbCr->RGB -> gmem -------
  {
    float ci[16];
    const float* cip = CI + (oddl ? 16 : 0);
#pragma unroll
    for (int t = 0; t < 16; ++t) ci[t] = cip[t];

    float* __restrict__ qr = out + img;
    float* __restrict__ qg = out + img + plane;
    float* __restrict__ qb2 = out + img + 2 * plane;

#pragma unroll
    for (int it = 0; it < 2; ++it) {
      int i = tid + it * 256;
      int row = i >> 4;
      int c4 = (i & 15) << 2;
      int s = row * 64 + swzc(c4);

      float y[4], cb[4], cr[4];
      float4 t4;
      t4 = *(const float4*)&sm[s];
      y[0]=t4.x; y[1]=t4.y; y[2]=t4.z; y[3]=t4.w;
      half_idct(y, ci, sgn);
      t4 = *(const float4*)&sm[PL + s];
      cb[0]=t4.x; cb[1]=t4.y; cb[2]=t4.z; cb[3]=t4.w;
      half_idct(cb, ci, sgn);
      t4 = *(const float4*)&sm[2 * PL + s];
      cr[0]=t4.x; cr[1]=t4.y; cr[2]=t4.z; cr[3]=t4.w;
      half_idct(cr, ci, sgn);

      float R[4], G[4], B[4];
#pragma unroll
      for (int q = 0; q < 4; ++q) {
        float y128 = y[q] + 128.f;      // recon is centered (DC trick)
        float r = fmaf(1.402f, cr[q], y128);
        float gg = fmaf(-0.714136f, cr[q], fmaf(-0.344136f, cb[q], y128));
        float b = fmaf(1.772f, cb[q], y128);
        const float inv255 = 1.0f / 255.0f;
        R[q] = fminf(fmaxf(r, 0.f), 255.f) * inv255;
        G[q] = fminf(fmaxf(gg, 0.f), 255.f) * inv255;
        B[q] = fminf(fmaxf(b, 0.f), 255.f) * inv255;
      }
      size_t g = (size_t)(gy0 + row) * Ww + (gx0 + c4);
      float4 ro = oddl ? make_float4(R[3], R[2], R[1], R[0]) : make_float4(R[0], R[1], R[2], R[3]);
      float4 go = oddl ? make_float4(G[3], G[2], G[1], G[0]) : make_float4(G[0], G[1], G[2], G[3]);
      float4 bo = oddl ? make_float4(B[3], B[2], B[1], B[0]) : make_float4(B[0], B[1], B[2], B[3]);
      *(float4*)(qr + g)  = ro;
      *(float4*)(qg + g)  = go;
      *(float4*)(qb2 + g) = bo;
    }
  }
}

} // namespace

extern "C" void kernel_launch(void* const* d_in, const int* in_sizes, int n_in,
                              void* d_out, int out_size) {
  (void)in_sizes; (void)n_in; (void)out_size;
  const float* in = (const float*)d_in[0];
  float* out = (float*)d_out;
  constexpr int SMEM = (3 * PL + 256) * 4;   // 25600 bytes
  static bool attr_set = false;
  if (!attr_set) {
    cudaFuncSetAttribute(jpeg_kernel, cudaFuncAttributeMaxDynamicSharedMemorySize, SMEM);
    attr_set = true;
  }
  dim3 grid(Ww / TW, Hh / TH, 16);
  jpeg_kernel<<<grid, 256, SMEM>>>(in, out);
}

// round 10
// speedup vs baseline: 1.1519x; 1.0144x over previous
#include <cuda_runtime.h>

// JPEG compress/decompress (DiffJPEG, factor=1.0) for [16,3,512,512] fp32 in [-1,1].
// One CTA = one 64x32 tile, 256 threads, 4 CTAs/SM.
// Phase 1: gmem -> YCbCr -> lane-pair half row-DCT -> smem (permuted freq slots)
// Phase 2: conflict-free LDS.128 (v2.u64) column pass, f32x2 packed math:
//          col DCT + diff-round quant (magic RNE) + col IDCT.
// Phase 3: smem -> half row-IDCT (coeffs pre-scaled by 1/255) -> YCbCr->RGB
//          via __saturatef -> gmem.
// DC trick: subtract 128*64 from the DC coefficient; re-add (128/255) at output.

namespace {

constexpr int Hh = 512;
constexpr int Ww = 512;
constexpr int TW = 64;
constexpr int TH = 32;
constexpr int PL = TW * TH;   // 2048 floats per channel plane

typedef unsigned long long u64;

__device__ __forceinline__ u64 F2PK(float a, float b) {
  u64 r; asm("mov.b64 %0,{%1,%2};" : "=l"(r) : "f"(a), "f"(b)); return r;
}
__device__ __forceinline__ u64 FMA2(u64 a, u64 b, u64 c) {
  u64 d; asm("fma.rn.f32x2 %0,%1,%2,%3;" : "=l"(d) : "l"(a), "l"(b), "l"(c)); return d;
}
__device__ __forceinline__ u64 ADD2(u64 a, u64 b) {
  u64 d; asm("add.rn.f32x2 %0,%1,%2;" : "=l"(d) : "l"(a), "l"(b)); return d;
}
__device__ __forceinline__ u64 SUB2(u64 a, u64 b) {
  u64 d; asm("sub.rn.f32x2 %0,%1,%2;" : "=l"(d) : "l"(a), "l"(b)); return d;
}
__device__ __forceinline__ u64 MUL2(u64 a, u64 b) {
  u64 d; asm("mul.rn.f32x2 %0,%1,%2;" : "=l"(d) : "l"(a), "l"(b)); return d;
}

// Forward half-transform coefs: CF[p][m][k] = Dm[2m+p][k], k=0..3
__constant__ float CF[32] = {
  1.f,          1.f,          1.f,          1.f,
  0.92387953f,  0.38268343f, -0.38268343f, -0.92387953f,
  0.70710678f, -0.70710678f, -0.70710678f,  0.70710678f,
  0.38268343f, -0.92387953f,  0.92387953f, -0.38268343f,
  0.98078528f,  0.83146961f,  0.55557023f,  0.19509032f,
  0.83146961f, -0.19509032f, -0.98078528f, -0.55557023f,
  0.55557023f, -0.98078528f,  0.19509032f,  0.83146961f,
  0.19509032f, -0.55557023f,  0.83146961f, -0.98078528f,
};
// Inverse half-transform coefs: CI[p][k][m] = Dm[2m+p][k]
__constant__ float CI[32] = {
  1.f,  0.92387953f,  0.70710678f,  0.38268343f,
  1.f,  0.38268343f, -0.70710678f, -0.92387953f,
  1.f, -0.38268343f, -0.70710678f,  0.92387953f,
  1.f, -0.92387953f,  0.70710678f, -0.38268343f,
  0.98078528f,  0.83146961f,  0.55557023f,  0.19509032f,
  0.83146961f, -0.19509032f, -0.98078528f, -0.55557023f,
  0.55557023f, -0.98078528f,  0.19509032f,  0.83146961f,
  0.19509032f, -0.55557023f,  0.83146961f, -0.98078528f,
};

__device__ static const float QY[64] = {
  16, 11, 10, 16, 24, 40, 51, 61,
  12, 12, 14, 19, 26, 58, 60, 55,
  14, 13, 16, 24, 40, 57, 69, 56,
  14, 17, 22, 29, 51, 87, 80, 62,
  18, 22, 37, 56, 68, 109, 103, 77,
  24, 35, 55, 64, 81, 104, 113, 92,
  49, 64, 78, 87, 103, 121, 120, 101,
  72, 92, 95, 98, 112, 100, 103, 99
};
__device__ static const float QC[64] = {
  17, 18, 24, 47, 99, 99, 99, 99,
  18, 21, 26, 66, 99, 99, 99, 99,
  24, 26, 56, 99, 99, 99, 99, 99,
  47, 66, 99, 99, 99, 99, 99, 99,
  99, 99, 99, 99, 99, 99, 99, 99,
  99, 99, 99, 99, 99, 99, 99, 99,
  99, 99, 99, 99, 99, 99, 99, 99,
  99, 99, 99, 99, 99, 99, 99, 99
};

__device__ __forceinline__ int swzc(int c) { return c ^ ((c & 32) >> 3); }

// Packed coefficient indices (positive only; signs via SUB2)
enum { K_C4 = 0, K_C2, K_C6, K_C1, K_C3, K_C5, K_C7, K_NUM };

// Packed 8-point DCT-II (two independent columns per u64)
__device__ __forceinline__ void dct2(u64* v, const u64* C) {
  u64 e0 = ADD2(v[0], v[7]), e1 = ADD2(v[1], v[6]);
  u64 e2 = ADD2(v[2], v[5]), e3 = ADD2(v[3], v[4]);
  u64 o0 = SUB2(v[0], v[7]), o1 = SUB2(v[1], v[6]);
  u64 o2 = SUB2(v[2], v[5]), o3 = SUB2(v[3], v[4]);
  u64 s03 = ADD2(e0, e3), s12 = ADD2(e1, e2);
  u64 d03 = SUB2(e0, e3), d12 = SUB2(e1, e2);
  v[0] = ADD2(s03, s12);
  v[4] = MUL2(C[K_C4], SUB2(s03, s12));
  v[2] = FMA2(C[K_C6], d12, MUL2(C[K_C2], d03));
  v[6] = SUB2(MUL2(C[K_C6], d03), MUL2(C[K_C2], d12));
  v[1] = FMA2(C[K_C7], o3, FMA2(C[K_C5], o2, FMA2(C[K_C3], o1, MUL2(C[K_C1], o0))));
  v[3] = SUB2(MUL2(C[K_C3], o0),
              FMA2(C[K_C7], o1, FMA2(C[K_C1], o2, MUL2(C[K_C5], o3))));
  v[5] = SUB2(FMA2(C[K_C7], o2, FMA2(C[K_C3], o3, MUL2(C[K_C5], o0))),
              MUL2(C[K_C1], o1));
  v[7] = SUB2(FMA2(C[K_C3], o2, MUL2(C[K_C7], o0)),
              FMA2(C[K_C1], o3, MUL2(C[K_C5], o1)));
}

// Packed 8-point IDCT (alpha folded into tables)
__device__ __forceinline__ void idct2(u64* v, const u64* C) {
  u64 t = MUL2(C[K_C4], v[4]);
  u64 p = ADD2(v[0], t);
  u64 m = SUB2(v[0], t);
  u64 u1 = FMA2(C[K_C6], v[6], MUL2(C[K_C2], v[2]));
  u64 u2 = SUB2(MUL2(C[K_C6], v[2]), MUL2(C[K_C2], v[6]));
  u64 ev0 = ADD2(p, u1), ev3 = SUB2(p, u1);
  u64 ev1 = ADD2(m, u2), ev2 = SUB2(m, u2);
  u64 i1 = v[1], i3 = v[3], i5 = v[5], i7 = v[7];
  u64 od0 = FMA2(C[K_C7], i7, FMA2(C[K_C5], i5, FMA2(C[K_C3], i3, MUL2(C[K_C1], i1))));
  u64 od1 = SUB2(MUL2(C[K_C3], i1),
                 FMA2(C[K_C7], i3, FMA2(C[K_C1], i5, MUL2(C[K_C5], i7))));
  u64 od2 = SUB2(FMA2(C[K_C7], i5, FMA2(C[K_C3], i7, MUL2(C[K_C5], i1))),
                 MUL2(C[K_C1], i3));
  u64 od3 = SUB2(FMA2(C[K_C3], i5, MUL2(C[K_C7], i1)),
                 FMA2(C[K_C1], i7, MUL2(C[K_C5], i3)));
  v[0] = ADD2(ev0, od0);  v[7] = SUB2(ev0, od0);
  v[1] = ADD2(ev1, od1);  v[6] = SUB2(ev1, od1);
  v[2] = ADD2(ev2, od2);  v[5] = SUB2(ev2, od2);
  v[3] = ADD2(ev3, od3);  v[4] = SUB2(ev3, od3);
}

// Lane-pair half row-DCT (even lane: natural px, odd lane: reversed px)
__device__ __forceinline__ void half_dct(float v[4], const float cf[16], float sgn) {
  float t0 = __shfl_xor_sync(0xffffffffu, v[0], 1);
  float t1 = __shfl_xor_sync(0xffffffffu, v[1], 1);
  float t2 = __shfl_xor_sync(0xffffffffu, v[2], 1);
  float t3 = __shfl_xor_sync(0xffffffffu, v[3], 1);
  float x0 = fmaf(sgn, v[0], t0);
  float x1 = fmaf(sgn, v[1], t1);
  float x2 = fmaf(sgn, v[2], t2);
  float x3 = fmaf(sgn, v[3], t3);
  v[0] = fmaf(cf[3],  x3, fmaf(cf[2],  x2, fmaf(cf[1],  x1, cf[0]  * x0)));
  v[1] = fmaf(cf[7],  x3, fmaf(cf[6],  x2, fmaf(cf[5],  x1, cf[4]  * x0)));
  v[2] = fmaf(cf[11], x3, fmaf(cf[10], x2, fmaf(cf[9],  x1, cf[8]  * x0)));
  v[3] = fmaf(cf[15], x3, fmaf(cf[14], x2, fmaf(cf[13], x1, cf[12] * x0)));
}

// Lane-pair half row-IDCT (even lane out: natural px, odd lane out: reversed px)
__device__ __forceinline__ void half_idct(float f[4], const float ci[16], float sgn) {
  float g0 = fmaf(ci[3],  f[3], fmaf(ci[2],  f[2], fmaf(ci[1],  f[1], ci[0]  * f[0])));
  float g1 = fmaf(ci[7],  f[3], fmaf(ci[6],  f[2], fmaf(ci[5],  f[1], ci[4]  * f[0])));
  float g2 = fmaf(ci[11], f[3], fmaf(ci[10], f[2], fmaf(ci[9],  f[1], ci[8]  * f[0])));
  float g3 = fmaf(ci[15], f[3], fmaf(ci[14], f[2], fmaf(ci[13], f[1], ci[12] * f[0])));
  float t0 = __shfl_xor_sync(0xffffffffu, g0, 1);
  float t1 = __shfl_xor_sync(0xffffffffu, g1, 1);
  float t2 = __shfl_xor_sync(0xffffffffu, g2, 1);
  float t3 = __shfl_xor_sync(0xffffffffu, g3, 1);
  f[0] = fmaf(sgn, g0, t0);
  f[1] = fmaf(sgn, g1, t1);
  f[2] = fmaf(sgn, g2, t2);
  f[3] = fmaf(sgn, g3, t3);
}

__global__ void __launch_bounds__(256, 4)
jpeg_kernel(const float* __restrict__ in, float* __restrict__ out) {
  extern __shared__ float sm[];         // 3*2048 planes + 128 SA + 128 SB
  float* sQA = sm + 3 * PL;             // slot-permuted: 0.25*au*av / Q
  float* sQB = sm + 3 * PL + 128;       // slot-permuted: 0.25*au*av * Q

  const int tid = threadIdx.x;
  const bool oddl = (tid & 1) != 0;
  const float sgn = oddl ? -1.f : 1.f;
  const int gx0 = blockIdx.x * TW;
  const int gy0 = blockIdx.y * TH;
  const size_t plane = (size_t)Hh * Ww;
  const size_t img = (size_t)blockIdx.z * 3 * plane;
  const float* __restrict__ pr = in + img;
  const float* __restrict__ pg = in + img + plane;
  const float* __restrict__ pb = in + img + 2 * plane;

  // ---- quant table fill (slot s holds freq perm[s] = {0,2,4,6,1,3,5,7}) ----
  if (tid < 128) {
    int tab = tid >> 6, uv = tid & 63, u = uv >> 3, s = uv & 7;
    int v = (s < 4) ? (s << 1) : ((s << 1) - 7);
    float a = 0.25f * (u ? 1.f : 0.70710678118654752f)
                    * (v ? 1.f : 0.70710678118654752f);
    float Q = tab ? QC[u * 8 + v] : QY[u * 8 + v];
    sQA[tid] = a / Q;
    sQB[tid] = a * Q;
  }

  // ------- Phase 1: gmem -> YCbCr -> half row-DCT -> smem (channel-serial) -------
  {
    float cf[16];
    const float* cfp = CF + (oddl ? 16 : 0);
#pragma unroll
    for (int t = 0; t < 16; ++t) cf[t] = cfp[t];

#pragma unroll
    for (int it = 0; it < 2; ++it) {
      int i = tid + it * 256;
      int row = i >> 4;                 // 0..31
      int c4 = (i & 15) << 2;
      size_t g = (size_t)(gy0 + row) * Ww + (gx0 + c4);
      float4 r4 = *(const float4*)(pr + g);
      float4 g4 = *(const float4*)(pg + g);
      float4 b4 = *(const float4*)(pb + g);

      // odd lanes reverse their 4 pixels (pixel order 8j+7..8j+4)
      float R[4], G[4], B[4];
      R[0] = oddl ? r4.w : r4.x;  R[1] = oddl ? r4.z : r4.y;
      R[2] = oddl ? r4.y : r4.z;  R[3] = oddl ? r4.x : r4.w;
      G[0] = oddl ? g4.w : g4.x;  G[1] = oddl ? g4.z : g4.y;
      G[2] = oddl ? g4.y : g4.z;  G[3] = oddl ? g4.x : g4.w;
      B[0] = oddl ? b4.w : b4.x;  B[1] = oddl ? b4.z : b4.y;
      B[2] = oddl ? b4.y : b4.z;  B[3] = oddl ? b4.x : b4.w;

      int s = row * 64 + swzc(c4);

      float ch[4];
#pragma unroll
      for (int q = 0; q < 4; ++q)   // Y ((x+1)/2*255 folded in)
        ch[q] = fmaf(38.1225f, R[q], fmaf(74.8425f, G[q], fmaf(14.535f, B[q], 127.5f)));
      half_dct(ch, cf, sgn);
      *(float4*)&sm[s] = make_float4(ch[0], ch[1], ch[2], ch[3]);

#pragma unroll
      for (int q = 0; q < 4; ++q)   // Cb
        ch[q] = fmaf(-21.51384f, R[q], fmaf(-42.23616f, G[q], fmaf(63.75f, B[q], 128.f)));
      half_dct(ch, cf, sgn);
      *(float4*)&sm[PL + s] = make_float4(ch[0], ch[1], ch[2], ch[3]);

#pragma unroll
      for (int q = 0; q < 4; ++q)   // Cr
        ch[q] = fmaf(63.75f, R[q], fmaf(-53.38272f, G[q], fmaf(-10.36728f, B[q], 128.f)));
      half_dct(ch, cf, sgn);
      *(float4*)&sm[2 * PL + s] = make_float4(ch[0], ch[1], ch[2], ch[3]);
    }
  }
  __syncthreads();

  // --- Phase 2: conflict-free v2.u64 column pass, packed f32x2 math ---
  // 192 active threads, each owns 4 adjacent columns (two packed pairs).
  if (tid < 192) {
    const int k = tid >> 6;
    const int idx = tid & 63;
    const int cg = idx & 15;
    const int br = idx >> 4;            // 0..3
    const int c4i = cg << 2;
    const int slot0 = c4i & 7;          // 0 or 4 (permuted freq slot of elem .x)
    const int koff = k ? 64 : 0;
    const int base = k * PL + br * 512 + swzc(c4i);

    u64 C[K_NUM];
    C[K_C4] = F2PK(0.70710678f, 0.70710678f);
    C[K_C2] = F2PK(0.92387953f, 0.92387953f);
    C[K_C6] = F2PK(0.38268343f, 0.38268343f);
    C[K_C1] = F2PK(0.98078528f, 0.98078528f);
    C[K_C3] = F2PK(0.83146961f, 0.83146961f);
    C[K_C5] = F2PK(0.55557023f, 0.55557023f);
    C[K_C7] = F2PK(0.19509032f, 0.19509032f);
    const u64 MAG = F2PK(12582912.f, 12582912.f);   // 1.5*2^23 (RNE magic)

    u64 A[8], Bv[8];
#pragma unroll
    for (int r = 0; r < 8; ++r) {
      ulonglong2 t = *(const ulonglong2*)&sm[base + r * 64];
      A[r] = t.x; Bv[r] = t.y;
    }
    dct2(A, C); dct2(Bv, C);
    if (slot0 == 0) A[0] = ADD2(A[0], F2PK(-8192.f, 0.f));  // DC offset

#pragma unroll
    for (int u = 0; u < 8; ++u) {
      ulonglong2 qa = *(const ulonglong2*)&sQA[koff + u * 8 + slot0];
      ulonglong2 qb = *(const ulonglong2*)&sQB[koff + u * 8 + slot0];
      u64 s0 = MUL2(A[u], qa.x);
      u64 r0 = SUB2(ADD2(s0, MAG), MAG);   // RNE round
      u64 d0 = SUB2(s0, r0);
      A[u] = MUL2(FMA2(MUL2(d0, d0), d0, r0), qb.x);
      u64 s1 = MUL2(Bv[u], qa.y);
      u64 r1 = SUB2(ADD2(s1, MAG), MAG);
      u64 d1 = SUB2(s1, r1);
      Bv[u] = MUL2(FMA2(MUL2(d1, d1), d1, r1), qb.y);
    }

    idct2(A, C); idct2(Bv, C);
#pragma unroll
    for (int r = 0; r < 8; ++r) {
      ulonglong2 t; t.x = A[r]; t.y = Bv[r];
      *(ulonglong2*)&sm[base + r * 64] = t;
    }
  }
  __syncthreads();

  // ------- Phase 3: smem -> half row-IDCT (x 1/255) -> RGB -> gmem -------
  {
    float ci[16];
    const float* cip = CI + (oddl ? 16 : 0);
    const float inv255 = 1.0f / 255.0f;
#pragma unroll
    for (int t = 0; t < 16; ++t) ci[t] = cip[t] * inv255;   // fold 1/255

    float* __restrict__ qr = out + img;
    float* __restrict__ qg = out + img + plane;
    float* __restrict__ qb2 = out + img + 2 * plane;

#pragma unroll
    for (int it = 0; it < 2; ++it) {
      int i = tid + it * 256;
      int row = i >> 4;
      int c4 = (i & 15) << 2;
      int s = row * 64 + swzc(c4);

      float y[4], cb[4], cr[4];
      float4 t4;
      t4 = *(const float4*)&sm[s];
      y[0]=t4.x; y[1]=t4.y; y[2]=t4.z; y[3]=t4.w;
      half_idct(y, ci, sgn);
      t4 = *(const float4*)&sm[PL + s];
      cb[0]=t4.x; cb[1]=t4.y; cb[2]=t4.z; cb[3]=t4.w;
      half_idct(cb, ci, sgn);
      t4 = *(const float4*)&sm[2 * PL + s];
      cr[0]=t4.x; cr[1]=t4.y; cr[2]=t4.z; cr[3]=t4.w;
      half_idct(cr, ci, sgn);

      float R[4], G[4], B[4];
#pragma unroll
      for (int q = 0; q < 4; ++q) {
        float y128 = y[q] + 0.501960784f;    // += 128/255 (DC trick, scaled)
        R[q] = __saturatef(fmaf(1.402f, cr[q], y128));
        G[q] = __saturatef(fmaf(-0.714136f, cr[q], fmaf(-0.344136f, cb[q], y128)));
        B[q] = __saturatef(fmaf(1.772f, cb[q], y128));
      }
      size_t g = (size_t)(gy0 + row) * Ww + (gx0 + c4);
      float4 ro = oddl ? make_float4(R[3], R[2], R[1], R[0]) : make_float4(R[0], R[1], R[2], R[3]);
      float4 go = oddl ? make_float4(G[3], G[2], G[1], G[0]) : make_float4(G[0], G[1], G[2], G[3]);
      float4 bo = oddl ? make_float4(B[3], B[2], B[1], B[0]) : make_float4(B[0], B[1], B[2], B[3]);
      *(float4*)(qr + g)  = ro;
      *(float4*)(qg + g)  = go;
      *(float4*)(qb2 + g) = bo;
    }
  }
}

} // namespace

extern "C" void kernel_launch(void* const* d_in, const int* in_sizes, int n_in,
                              void* d_out, int out_size) {
  (void)in_sizes; (void)n_in; (void)out_size;
  const float* in = (const float*)d_in[0];
  float* out = (float*)d_out;
  constexpr int SMEM = (3 * PL + 256) * 4;   // 25600 bytes
  static bool attr_set = false;
  if (!attr_set) {
    cudaFuncSetAttribute(jpeg_kernel, cudaFuncAttributeMaxDynamicSharedMemorySize, SMEM);
    attr_set = true;
  }
  dim3 grid(Ww / TW, Hh / TH, 16);
  jpeg_kernel<<<grid, 256, SMEM>>>(in, out);
}